// round 8
// baseline (speedup 1.0000x reference)
#include <cuda_runtime.h>
#include <cuda_fp16.h>
#include <cstdint>

// fullConv4d via fp16 mma.sync m16n8k16 (fp32 accum). M=spatial, N=co, K=ci16.
// CTA = (b, h, w-tile 2, d-tile 8). 8 warps = (wo 0-1) x (d-pair 0-3).
// Slab = 6 regions [kt 0..2][ci-half L/H], each [w''4][d''10][t24] x 16B rows:
// every ldmatrix matrix is 8 consecutive 16B rows starting at row%8==0 ->
// 128B-aligned contiguous -> minimal 4 wavefronts per LDSM.x4.
// Weights staged in B-fragment order: 1 LDS.128 per tap serves both co n-tiles.

#define ST_T 1
#define ST_D 24
#define ST_W 576
#define ST_H 13824
#define ST_C 331776

#define HALF_BYTES  15360                  // 960 rows * 16B
#define COPY_BYTES  30720                  // 2 halves
#define SLAB_BYTES  92160                  // 3 kt copies
#define WS_BYTES    13824                  // 27 taps * 512B
#define SMEM_BYTES  (SLAB_BYTES + WS_BYTES)  // 105984

static __device__ __forceinline__ uint32_t smem_u32(const void* p) {
    uint32_t a;
    asm("{ .reg .u64 t; cvta.to.shared.u64 t, %1; cvt.u32.u64 %0, t; }" : "=r"(a) : "l"(p));
    return a;
}

static __device__ __forceinline__ uint32_t pack2(float a, float b) {
    __half2 h = __floats2half2_rn(a, b);
    return *reinterpret_cast<uint32_t*>(&h);
}

static __device__ __forceinline__ void mma16816(float* d, uint32_t a0, uint32_t a1,
                                                uint32_t a2, uint32_t a3,
                                                uint32_t b0, uint32_t b1) {
    asm volatile(
        "mma.sync.aligned.m16n8k16.row.col.f32.f16.f16.f32 "
        "{%0,%1,%2,%3}, {%4,%5,%6,%7}, {%8,%9}, {%0,%1,%2,%3};"
        : "+f"(d[0]), "+f"(d[1]), "+f"(d[2]), "+f"(d[3])
        : "r"(a0), "r"(a1), "r"(a2), "r"(a3), "r"(b0), "r"(b1));
}

__global__ __launch_bounds__(256, 2)
void conv4d_hmma16a_kernel(const float* __restrict__ x,
                           const float* __restrict__ wgt,
                           const float* __restrict__ bias,
                           float* __restrict__ out) {
    extern __shared__ char smc[];
    const uint32_t slabAddr = smem_u32(smc);
    const uint32_t wsAddr   = slabAddr + SLAB_BYTES;

    const int tid = threadIdx.x;
    const int wid = tid >> 5;
    const int l   = tid & 31;
    const int g   = l >> 2;
    const int c   = l & 3;
    const int wo  = wid >> 2;
    const int dp  = wid & 3;

    // ---- decode block ----
    int bi = blockIdx.x;
    const int dt = bi % 3;  bi /= 3;
    const int wt = bi % 12; bi /= 12;
    const int h  = bi % 24; bi /= 24;
    const int b  = bi;
    const int d0 = dt * 8;
    const int w0 = wt * 2;
    const float* xb = x + (size_t)b * 16 * ST_C;

    // ldmatrix per-lane base: half = l>>4 (ci lo/hi), H-rows (lanes bit3) = +24 rows.
    const uint32_t aLane = slabAddr + (uint32_t)((l >> 4) * HALF_BYTES)
        + (uint32_t)(((wo * 10 + 2 * dp) * 24 + (l & 7) + ((l & 8) ? 24 : 0)) * 16);

    // ---- precompute staging slots (kh-invariant) ----
    // item i: o = ci-half, pp -> (w'' 0..3, d'' 0..9, gtIdx 0..25), gt = gtIdx-1.
    int      gOff[9];
    uint32_t sA0[9];
    uint32_t inR = 0, gV = 0, k0m = 0, k1m = 0, k2m = 0;
    #pragma unroll
    for (int k = 0; k < 9; ++k) {
        const int i = tid + k * 256;
        gOff[k] = 0; sA0[k] = 0;
        if (i < 2080) {
            const int o  = i & 1;
            const int pp = i >> 1;
            const int gtIdx = pp % 26;
            const int rr = pp / 26;
            const int dI = rr % 10;
            const int wI = rr / 10;
            inR |= (1u << k);
            if (gtIdx <= 23) k0m |= (1u << k);
            if (gtIdx >= 1 && gtIdx <= 24) k1m |= (1u << k);
            if (gtIdx >= 2) k2m |= (1u << k);
            sA0[k] = slabAddr + (uint32_t)(o * HALF_BYTES)
                     + (uint32_t)(((wI * 10 + dI) * 24 + gtIdx) * 16);
            const int gw = w0 + wI - 1, gd = d0 + dI - 1, gt = gtIdx - 1;
            if ((unsigned)gw < 24u && (unsigned)gd < 24u && (unsigned)gt < 24u) {
                gOff[k] = o * 8 * ST_C + gw * ST_W + gd * ST_D + gt;
                gV |= (1u << k);
            }
        }
    }

    float acc[3][2][4];
    #pragma unroll
    for (int j = 0; j < 3; ++j)
        #pragma unroll
        for (int u = 0; u < 2; ++u)
            #pragma unroll
            for (int q = 0; q < 4; ++q) acc[j][u][q] = 0.0f;

    for (int kh = 0; kh < 3; ++kh) {
        const int gh = h + kh - 1;
        if ((unsigned)gh >= 24u) continue;            // uniform across block

        __syncthreads();   // previous iteration's smem reads complete

        // ---- stage weights in B-fragment order: [tap][lane][b0,b1,b0',b1'] ----
        for (int i = tid; i < 864; i += 256) {
            const int tl = i >> 5, l5 = i & 31;
            const int gg = l5 >> 2, cc = (l5 & 3) << 1;
            const float* wp = wgt + kh * 27 + tl;
            #define WG(co, ci) wp[((co) * 16 + (ci)) * 81]
            const uint32_t r0 = pack2(WG(gg, cc),         WG(gg, cc + 1));
            const uint32_t r1 = pack2(WG(gg, cc + 8),     WG(gg, cc + 9));
            const uint32_t r2 = pack2(WG(gg + 8, cc),     WG(gg + 8, cc + 1));
            const uint32_t r3 = pack2(WG(gg + 8, cc + 8), WG(gg + 8, cc + 9));
            #undef WG
            asm volatile("st.shared.v4.b32 [%0], {%1,%2,%3,%4};"
                         :: "r"(wsAddr + (uint32_t)(tl * 512 + l5 * 16)),
                            "r"(r0), "r"(r1), "r"(r2), "r"(r3));
        }

        // ---- stage slab: gather 8 ci, write up to 3 kt-shifted copies ----
        const float* xh = xb + gh * ST_H;
        #pragma unroll
        for (int k = 0; k < 9; ++k) {
            if (inR & (1u << k)) {
                uint32_t v0 = 0, v1 = 0, v2 = 0, v3 = 0;
                if (gV & (1u << k)) {
                    const float* p = xh + gOff[k];
                    v0 = pack2(p[0],          p[ST_C]);
                    v1 = pack2(p[2 * ST_C],   p[3 * ST_C]);
                    v2 = pack2(p[4 * ST_C],   p[5 * ST_C]);
                    v3 = pack2(p[6 * ST_C],   p[7 * ST_C]);
                }
                if (k0m & (1u << k))
                    asm volatile("st.shared.v4.b32 [%0], {%1,%2,%3,%4};"
                                 :: "r"(sA0[k]), "r"(v0), "r"(v1), "r"(v2), "r"(v3));
                if (k1m & (1u << k))
                    asm volatile("st.shared.v4.b32 [%0], {%1,%2,%3,%4};"
                                 :: "r"(sA0[k] + COPY_BYTES - 16),
                                    "r"(v0), "r"(v1), "r"(v2), "r"(v3));
                if (k2m & (1u << k))
                    asm volatile("st.shared.v4.b32 [%0], {%1,%2,%3,%4};"
                                 :: "r"(sA0[k] + 2 * COPY_BYTES - 32),
                                    "r"(v0), "r"(v1), "r"(v2), "r"(v3));
            }
        }
        __syncthreads();

        // ---- compute: 27 taps x (1 LDS.128 + 3 LDSM.x4 + 6 HMMA) ----
        const uint32_t wLane = wsAddr + (uint32_t)(l * 16);
        #pragma unroll
        for (int tl = 0; tl < 27; ++tl) {
            const int kw = tl / 9, kd = (tl / 3) % 3, kt = tl % 3;
            uint32_t b0, b1, b2, b3;
            asm volatile("ld.shared.v4.b32 {%0,%1,%2,%3}, [%4];"
                         : "=r"(b0), "=r"(b1), "=r"(b2), "=r"(b3)
                         : "r"(wLane + (uint32_t)(tl * 512)));
            #pragma unroll
            for (int j = 0; j < 3; ++j) {
                const uint32_t P = (uint32_t)(kt * COPY_BYTES
                                              + (kw * 240 + kd * 24 + 8 * j) * 16);
                uint32_t a0, a1, a2, a3;
                asm volatile("ldmatrix.sync.aligned.m8n8.x4.shared.b16 {%0,%1,%2,%3}, [%4];"
                             : "=r"(a0), "=r"(a1), "=r"(a2), "=r"(a3)
                             : "r"(aLane + P));
                mma16816(acc[j][0], a0, a1, a2, a3, b0, b1);
                mma16816(acc[j][1], a0, a1, a2, a3, b2, b3);
            }
        }
    }

    // ---- epilogue ----
    float* ob = out + (size_t)b * 16 * ST_C + (size_t)h * ST_H + (size_t)(w0 + wo) * ST_W;
    const int dE = d0 + 2 * dp, dO = dE + 1;
    #pragma unroll
    for (int u = 0; u < 2; ++u) {
        const int co0 = u * 8 + 2 * c;
        const float b0v = bias[co0];
        const float b1v = bias[co0 + 1];
        #pragma unroll
        for (int j = 0; j < 3; ++j) {
            const int t = 8 * j + g;
            ob[(size_t)co0 * ST_C + (size_t)dE * ST_D + t]       = acc[j][u][0] + b0v;
            ob[(size_t)(co0 + 1) * ST_C + (size_t)dE * ST_D + t] = acc[j][u][1] + b1v;
            ob[(size_t)co0 * ST_C + (size_t)dO * ST_D + t]       = acc[j][u][2] + b0v;
            ob[(size_t)(co0 + 1) * ST_C + (size_t)dO * ST_D + t] = acc[j][u][3] + b1v;
        }
    }
}

extern "C" void kernel_launch(void* const* d_in, const int* in_sizes, int n_in,
                              void* d_out, int out_size) {
    const float* x   = (const float*)d_in[0];
    const float* w   = (const float*)d_in[1];
    const float* bia = (const float*)d_in[2];
    float* out       = (float*)d_out;

    cudaFuncSetAttribute(conv4d_hmma16a_kernel,
                         cudaFuncAttributeMaxDynamicSharedMemorySize, SMEM_BYTES);

    const int grid = 2 * 24 * 12 * 3;   // 1728
    conv4d_hmma16a_kernel<<<grid, 256, SMEM_BYTES>>>(x, w, bia, out);
}

// round 9
// speedup vs baseline: 2.0356x; 2.0356x over previous
#include <cuda_runtime.h>
#include <cuda_fp16.h>
#include <cstdint>

// fullConv4d via fp16 mma.sync m16n8k16 (fp32 accum). M=spatial, N=co, K=ci16.
// R9: prep kernels pre-convert x -> fp16 point-major [pt][ci16] (21MB device buf) and
// weights -> B-fragment order. Main kernel double-buffers the slab via cp.async (16B,
// zero-fill for halo) pipelined behind compute. Compute loop identical to R7.

#define ST_T 1
#define ST_D 24
#define ST_W 576
#define ST_H 13824
#define ST_C 331776

#define SLABB   33280                       // 1040 pts * 32B
#define WSB     41472                       // 81 taps * 512B
#define SMEM_BYTES (2 * SLABB + WSB)        // 108032

__device__ uint4 g_xh[1327104];             // 663552 points * 32B  (fp16, ci-major 16)
__device__ uint4 g_wf[2592];                // 81 taps * 32 lanes * 16B

static __device__ __forceinline__ uint32_t smem_u32(const void* p) {
    uint32_t a;
    asm("{ .reg .u64 t; cvta.to.shared.u64 t, %1; cvt.u32.u64 %0, t; }" : "=r"(a) : "l"(p));
    return a;
}

static __device__ __forceinline__ uint32_t pack2(float a, float b) {
    __half2 h = __floats2half2_rn(a, b);
    return *reinterpret_cast<uint32_t*>(&h);
}

static __device__ __forceinline__ void cpa16(uint32_t dst, const void* src, uint32_t srcsz) {
    asm volatile("cp.async.cg.shared.global [%0], [%1], 16, %2;"
                 :: "r"(dst), "l"(src), "r"(srcsz));
}

static __device__ __forceinline__ void mma16816(float* d, uint32_t a0, uint32_t a1,
                                                uint32_t a2, uint32_t a3,
                                                uint32_t b0, uint32_t b1) {
    asm volatile(
        "mma.sync.aligned.m16n8k16.row.col.f32.f16.f16.f32 "
        "{%0,%1,%2,%3}, {%4,%5,%6,%7}, {%8,%9}, {%0,%1,%2,%3};"
        : "+f"(d[0]), "+f"(d[1]), "+f"(d[2]), "+f"(d[3])
        : "r"(a0), "r"(a1), "r"(a2), "r"(a3), "r"(b0), "r"(b1));
}

// ---- prep 1: x[b][ci][h][w][d][t] fp32 -> g_xh[(b,h,w,d,t)][ci16] fp16 ----
__global__ __launch_bounds__(256)
void prep_x_kernel(const float* __restrict__ x) {
    const int idx = blockIdx.x * 256 + threadIdx.x;          // 663552 points
    int r = idx;
    const int t = r % 24; r /= 24;
    const int d = r % 24; r /= 24;
    const int w = r % 24; r /= 24;
    const int h = r % 24;
    const int b = r / 24;
    const float* p = x + (size_t)b * 16 * ST_C + h * ST_H + w * ST_W + d * ST_D + t;
    uint32_t v[8];
    #pragma unroll
    for (int j = 0; j < 8; ++j)
        v[j] = pack2(p[(2 * j) * ST_C], p[(2 * j + 1) * ST_C]);
    g_xh[idx * 2]     = make_uint4(v[0], v[1], v[2], v[3]);
    g_xh[idx * 2 + 1] = make_uint4(v[4], v[5], v[6], v[7]);
}

// ---- prep 2: weights -> B-fragment order g_wf[tap][lane] ----
__global__ __launch_bounds__(256)
void prep_w_kernel(const float* __restrict__ wgt) {
    for (int i = threadIdx.x; i < 2592; i += 256) {
        const int tl = i >> 5, l5 = i & 31;
        const int gg = l5 >> 2, cc = (l5 & 3) << 1;
        const float* wp = wgt + tl;
        #define WG(co, ci) wp[((co) * 16 + (ci)) * 81]
        const uint32_t r0 = pack2(WG(gg, cc),         WG(gg, cc + 1));
        const uint32_t r1 = pack2(WG(gg, cc + 8),     WG(gg, cc + 9));
        const uint32_t r2 = pack2(WG(gg + 8, cc),     WG(gg + 8, cc + 1));
        const uint32_t r3 = pack2(WG(gg + 8, cc + 8), WG(gg + 8, cc + 9));
        #undef WG
        g_wf[i] = make_uint4(r0, r1, r2, r3);
    }
}

// ---- main ----
__global__ __launch_bounds__(256, 2)
void conv4d_hmma16p_kernel(const float* __restrict__ bias,
                           float* __restrict__ out) {
    extern __shared__ char smc[];
    const uint32_t slabAddr = smem_u32(smc);                 // buf0 | buf1 | ws
    const uint32_t wsAddr   = slabAddr + 2 * SLABB;

    const int tid = threadIdx.x;
    const int wid = tid >> 5;
    const int l   = tid & 31;
    const int g   = l >> 2;
    const int c   = l & 3;
    const int wo  = wid >> 2;
    const int dp  = wid & 3;

    int bi = blockIdx.x;
    const int dt = bi % 3;  bi /= 3;
    const int wt = bi % 12; bi /= 12;
    const int h  = bi % 24; bi /= 24;
    const int b  = bi;
    const int d0 = dt * 8;
    const int w0 = wt * 2;

    // ldmatrix per-lane offset within a slab buffer (R7 rowmap: H rows = +26)
    const int rowmap = (l & 8) ? (26 + (l & 7)) : (l & 7);
    const uint32_t aOff = (uint32_t)((wo * 260 + dp * 52 + rowmap) * 32 + (l >> 4) * 16);

    // ---- precompute staging slots ----
    uint32_t dstOff[9];
    int      srcRest[9];
    uint32_t inR = 0, gV = 0;
    #pragma unroll
    for (int k = 0; k < 9; ++k) {
        const int i = tid + k * 256;
        dstOff[k] = 0; srcRest[k] = 0;
        if (i < 2080) {
            const int o  = i & 1;
            const int pt = i >> 1;
            const int tI = pt % 26;
            const int rr = pt / 26;
            const int dI = rr % 10;
            const int wI = rr / 10;
            inR |= (1u << k);
            dstOff[k] = (uint32_t)(pt * 32 + o * 16);
            const int gw = w0 + wI - 1, gd = d0 + dI - 1, gt = tI - 1;
            if ((unsigned)gw < 24u && (unsigned)gd < 24u && (unsigned)gt < 24u) {
                srcRest[k] = (gw * 576 + gd * 24 + gt) * 32 + o * 16;
                gV |= (1u << k);
            }
        }
    }

    // valid kh planes
    int khs[3], nkh = 0;
    #pragma unroll
    for (int kh = 0; kh < 3; ++kh)
        if ((unsigned)(h + kh - 1) < 24u) khs[nkh++] = kh;

    const char* xhBase = (const char*)g_xh;

    // stage_slab lambda
    auto stage_slab = [&](int kh, uint32_t bufAddr) {
        const long long planeOff = (long long)((b * 24 + (h + kh - 1)) * 13824) * 32;
        const char* sp = xhBase + planeOff;
        #pragma unroll
        for (int k = 0; k < 9; ++k) {
            if (inR & (1u << k))
                cpa16(bufAddr + dstOff[k], sp + srcRest[k],
                      (gV & (1u << k)) ? 16u : 0u);
        }
    };

    // group 0: weights + slab khs[0]
    {
        const char* wf = (const char*)g_wf;
        #pragma unroll
        for (int k = 0; k < 11; ++k) {
            const int i = tid + k * 256;
            if (i < 2592) cpa16(wsAddr + (uint32_t)(i * 16), wf + i * 16, 16u);
        }
        stage_slab(khs[0], slabAddr);
        asm volatile("cp.async.commit_group;" ::: "memory");
    }
    // group 1: slab khs[1]
    if (nkh > 1) {
        stage_slab(khs[1], slabAddr + SLABB);
        asm volatile("cp.async.commit_group;" ::: "memory");
    }
    int issued = (nkh > 1) ? 2 : 1;

    float acc[3][2][4];
    #pragma unroll
    for (int j = 0; j < 3; ++j)
        #pragma unroll
        for (int u = 0; u < 2; ++u)
            #pragma unroll
            for (int q = 0; q < 4; ++q) acc[j][u][q] = 0.0f;

    for (int i = 0; i < nkh; ++i) {
        if (issued - i == 2) { asm volatile("cp.async.wait_group 1;" ::: "memory"); }
        else                 { asm volatile("cp.async.wait_group 0;" ::: "memory"); }
        __syncthreads();

        const uint32_t bufAddr = slabAddr + (uint32_t)((i & 1) * SLABB);
        const uint32_t aLane   = bufAddr + aOff;
        const uint32_t wLane   = wsAddr + (uint32_t)(khs[i] * 27 * 512 + l * 16);

        #pragma unroll
        for (int tl = 0; tl < 27; ++tl) {
            const int kw = tl / 9, kd = (tl / 3) % 3, kt = tl % 3;
            uint32_t b0, b1, b2, b3;
            asm volatile("ld.shared.v4.b32 {%0,%1,%2,%3}, [%4];"
                         : "=r"(b0), "=r"(b1), "=r"(b2), "=r"(b3)
                         : "r"(wLane + (uint32_t)(tl * 512)));
            #pragma unroll
            for (int j = 0; j < 3; ++j) {
                const uint32_t P = (uint32_t)((kw * 260 + kd * 26 + kt + 8 * j) * 32);
                uint32_t a0, a1, a2, a3;
                asm volatile("ldmatrix.sync.aligned.m8n8.x4.shared.b16 {%0,%1,%2,%3}, [%4];"
                             : "=r"(a0), "=r"(a1), "=r"(a2), "=r"(a3)
                             : "r"(aLane + P));
                mma16816(acc[j][0], a0, a1, a2, a3, b0, b1);
                mma16816(acc[j][1], a0, a1, a2, a3, b2, b3);
            }
        }

        if (issued < nkh) {               // nkh==3, after compute of i==0: refill buf0
            __syncthreads();
            stage_slab(khs[2], slabAddr);
            asm volatile("cp.async.commit_group;" ::: "memory");
            issued = 3;
        }
    }

    // ---- epilogue ----
    float* ob = out + (size_t)b * 16 * ST_C + (size_t)h * ST_H + (size_t)(w0 + wo) * ST_W;
    const int dE = d0 + 2 * dp, dO = dE + 1;
    #pragma unroll
    for (int u = 0; u < 2; ++u) {
        const int co0 = u * 8 + 2 * c;
        const float b0v = bias[co0];
        const float b1v = bias[co0 + 1];
        #pragma unroll
        for (int j = 0; j < 3; ++j) {
            const int t = 8 * j + g;
            ob[(size_t)co0 * ST_C + (size_t)dE * ST_D + t]       = acc[j][u][0] + b0v;
            ob[(size_t)(co0 + 1) * ST_C + (size_t)dE * ST_D + t] = acc[j][u][1] + b1v;
            ob[(size_t)co0 * ST_C + (size_t)dO * ST_D + t]       = acc[j][u][2] + b0v;
            ob[(size_t)(co0 + 1) * ST_C + (size_t)dO * ST_D + t] = acc[j][u][3] + b1v;
        }
    }
}

extern "C" void kernel_launch(void* const* d_in, const int* in_sizes, int n_in,
                              void* d_out, int out_size) {
    const float* x   = (const float*)d_in[0];
    const float* w   = (const float*)d_in[1];
    const float* bia = (const float*)d_in[2];
    float* out       = (float*)d_out;

    prep_x_kernel<<<2592, 256>>>(x);
    prep_w_kernel<<<1, 256>>>(w);

    cudaFuncSetAttribute(conv4d_hmma16p_kernel,
                         cudaFuncAttributeMaxDynamicSharedMemorySize, SMEM_BYTES);
    conv4d_hmma16p_kernel<<<1728, 256, SMEM_BYTES>>>(bia, out);
}